// round 4
// baseline (speedup 1.0000x reference)
#include <cuda_runtime.h>
#include <math.h>

#define B_  8
#define S_  1024
#define D_  1024
#define H_  16
#define DK_ 64

// Scratch (device globals: no allocation allowed in kernel_launch)
__device__ float g_q[B_*S_*D_];
__device__ float g_k[B_*S_*D_];
__device__ float g_v[B_*S_*D_];
__device__ float g_att[B_*S_*D_];

__device__ __forceinline__ unsigned f2tf32(float x) {
    unsigned u;
    asm("cvt.rna.tf32.f32 %0, %1;" : "=r"(u) : "f"(x));
    return u;
}

// Branchless exp2 for z <= 0, FFMA/ALU only (no MUFU).
// NaN input -> fmaxf picks -126 -> ~0. z clamped at -126 (flush to ~0).
__device__ __forceinline__ float exp2c(float z) {
    z = fmaxf(z, -126.0f);
    const float magic = 12582912.0f;           // 1.5*2^23
    float r = z + magic;
    int   n = __float_as_int(r) - __float_as_int(magic);
    float f = z - (r - magic);                 // f in [-0.5, 0.5]
    float c = 0.0013333558f;
    c = fmaf(c, f, 0.0096181291f);
    c = fmaf(c, f, 0.0555041087f);
    c = fmaf(c, f, 0.2402265069f);
    c = fmaf(c, f, 0.6931471806f);
    c = fmaf(c, f, 1.0f);
    return c * __int_as_float((n + 127) << 23);
}

// ---------------------------------------------------------------------------
// tf32 tensor-core GEMM: C[M,N] = A[M,K] @ W[N,K]^T + bias[N]  (unchanged R2)
// ---------------------------------------------------------------------------
#define TILE_F 4608   // 128*36 floats per smem tile

__global__ void __launch_bounds__(256) gemm_tf32(
    const float* __restrict__ A, const float* __restrict__ W,
    const float* __restrict__ bias, float* __restrict__ C,
    int M, int N, int K)
{
    extern __shared__ float sm[];
    const int tid  = threadIdx.x;
    const int warp = tid >> 5, lane = tid & 31;
    const int wm = warp & 1, wn = warp >> 1;
    const int g = lane >> 2, t = lane & 3;
    const int m0 = blockIdx.y << 7, n0 = blockIdx.x << 7;

    const int lrow = tid >> 3;
    const int lcol = (tid & 7) << 2;

    float acc[4][4][4];
#pragma unroll
    for (int i = 0; i < 4; i++)
#pragma unroll
        for (int j = 0; j < 4; j++)
#pragma unroll
            for (int c = 0; c < 4; c++) acc[i][j][c] = 0.f;

    const int NCHUNK = K >> 5;

    {
        float* sA = sm;
        float* sW = sm + TILE_F;
#pragma unroll
        for (int l = 0; l < 4; l++) {
            const int row = lrow + (l << 5);
            unsigned da = (unsigned)__cvta_generic_to_shared(&sA[row * 36 + lcol]);
            unsigned dw = (unsigned)__cvta_generic_to_shared(&sW[row * 36 + lcol]);
            const float* ga = A + (size_t)(m0 + row) * K + lcol;
            const float* gw = W + (size_t)(n0 + row) * K + lcol;
            asm volatile("cp.async.cg.shared.global [%0], [%1], 16;" :: "r"(da), "l"(ga));
            asm volatile("cp.async.cg.shared.global [%0], [%1], 16;" :: "r"(dw), "l"(gw));
        }
        asm volatile("cp.async.commit_group;");
    }

    for (int kc = 0; kc < NCHUNK; kc++) {
        if (kc + 1 < NCHUNK) {
            const int k0 = (kc + 1) << 5;
            float* sA = sm + ((kc + 1) & 1) * (2 * TILE_F);
            float* sW = sA + TILE_F;
#pragma unroll
            for (int l = 0; l < 4; l++) {
                const int row = lrow + (l << 5);
                unsigned da = (unsigned)__cvta_generic_to_shared(&sA[row * 36 + lcol]);
                unsigned dw = (unsigned)__cvta_generic_to_shared(&sW[row * 36 + lcol]);
                const float* ga = A + (size_t)(m0 + row) * K + k0 + lcol;
                const float* gw = W + (size_t)(n0 + row) * K + k0 + lcol;
                asm volatile("cp.async.cg.shared.global [%0], [%1], 16;" :: "r"(da), "l"(ga));
                asm volatile("cp.async.cg.shared.global [%0], [%1], 16;" :: "r"(dw), "l"(gw));
            }
            asm volatile("cp.async.commit_group;");
            asm volatile("cp.async.wait_group 1;");
        } else {
            asm volatile("cp.async.wait_group 0;");
        }
        __syncthreads();

        const float* sA = sm + (kc & 1) * (2 * TILE_F);
        const float* sW = sA + TILE_F;

#pragma unroll
        for (int ks = 0; ks < 4; ks++) {
            const int kk = ks << 3;
            unsigned af[4][4], bf[4][2];
#pragma unroll
            for (int ma = 0; ma < 4; ma++) {
                const int r0 = wm * 64 + ma * 16 + g;
                af[ma][0] = f2tf32(sA[r0 * 36 + kk + t]);
                af[ma][1] = f2tf32(sA[(r0 + 8) * 36 + kk + t]);
                af[ma][2] = f2tf32(sA[r0 * 36 + kk + t + 4]);
                af[ma][3] = f2tf32(sA[(r0 + 8) * 36 + kk + t + 4]);
            }
#pragma unroll
            for (int na = 0; na < 4; na++) {
                const int rn = wn * 32 + na * 8 + g;
                bf[na][0] = f2tf32(sW[rn * 36 + kk + t]);
                bf[na][1] = f2tf32(sW[rn * 36 + kk + t + 4]);
            }
#pragma unroll
            for (int ma = 0; ma < 4; ma++)
#pragma unroll
                for (int na = 0; na < 4; na++) {
                    asm volatile(
                        "mma.sync.aligned.m16n8k8.row.col.f32.tf32.tf32.f32 "
                        "{%0,%1,%2,%3}, {%4,%5,%6,%7}, {%8,%9}, {%0,%1,%2,%3};"
                        : "+f"(acc[ma][na][0]), "+f"(acc[ma][na][1]),
                          "+f"(acc[ma][na][2]), "+f"(acc[ma][na][3])
                        : "r"(af[ma][0]), "r"(af[ma][1]), "r"(af[ma][2]), "r"(af[ma][3]),
                          "r"(bf[na][0]), "r"(bf[na][1]));
                }
        }
        __syncthreads();
    }

#pragma unroll
    for (int na = 0; na < 4; na++) {
        const int col = n0 + wn * 32 + na * 8 + 2 * t;
        const float bx = bias[col], by = bias[col + 1];
#pragma unroll
        for (int ma = 0; ma < 4; ma++) {
            const int row0 = m0 + wm * 64 + ma * 16 + g;
            float2 r;
            r.x = acc[ma][na][0] + bx; r.y = acc[ma][na][1] + by;
            *(float2*)(C + (size_t)row0 * N + col) = r;
            r.x = acc[ma][na][2] + bx; r.y = acc[ma][na][3] + by;
            *(float2*)(C + (size_t)(row0 + 8) * N + col) = r;
        }
    }
}

// ---------------------------------------------------------------------------
// Tensor-core flash attention (tf32 mma + FFMA softmax).
// CTA = 128 threads = 4 warps; each warp owns 16 q-rows. Q frags in regs.
// K/V double-buffered via cp.async, stride-68 smem rows (conflict-free frags).
// P round-trips through smem as pre-converted tf32 bits.
// ---------------------------------------------------------------------------
#define FT 4352   // 64*68 floats per K/V/P tile

__global__ void __launch_bounds__(128) flash_tc(
    const float* __restrict__ Q, const float* __restrict__ Kp,
    const float* __restrict__ V, const int* __restrict__ mask,
    float* __restrict__ O)
{
    extern __shared__ float smf[];
    float* KsB = smf;            // [2][64][68]
    float* VsB = smf + 2 * FT;   // [2][64][68]
    float* Ps  = smf + 4 * FT;   // [64][68]  (also Q staging)

    const int tid  = threadIdx.x;
    const int w    = tid >> 5, lane = tid & 31;
    const int g    = lane >> 2, t = lane & 3;
    const int q0   = (int)blockIdx.x << 6;
    const int bh   = blockIdx.y;
    const int b    = bh >> 4, h = bh & 15;
    const float SCL = 0.125f * 1.4426950408889634f;  // scale * log2(e)

    // prefetch K/V tile 0
    {
#pragma unroll
        for (int l = 0; l < 8; l++) {
            const int f = tid + (l << 7);
            const int row = f >> 4, c4 = (f & 15) << 2;
            const size_t src = (size_t)(b * S_ + row) * D_ + h * DK_ + c4;
            unsigned dk = (unsigned)__cvta_generic_to_shared(&KsB[row * 68 + c4]);
            unsigned dv = (unsigned)__cvta_generic_to_shared(&VsB[row * 68 + c4]);
            asm volatile("cp.async.cg.shared.global [%0], [%1], 16;" :: "r"(dk), "l"(Kp + src));
            asm volatile("cp.async.cg.shared.global [%0], [%1], 16;" :: "r"(dv), "l"(V + src));
        }
        asm volatile("cp.async.commit_group;");
    }

    // stage Q into Ps, then load Q fragments into registers (tf32)
#pragma unroll
    for (int l = 0; l < 8; l++) {
        const int f = tid + (l << 7);
        const int row = f >> 4, c4 = (f & 15) << 2;
        *(float4*)&Ps[row * 68 + c4] =
            *(const float4*)(Q + (size_t)(b * S_ + q0 + row) * D_ + h * DK_ + c4);
    }
    __syncthreads();

    const int r0 = w * 16 + g;
    unsigned qf[8][4];
#pragma unroll
    for (int kf = 0; kf < 8; kf++) {
        const int kk = kf << 3;
        qf[kf][0] = f2tf32(Ps[r0 * 68 + kk + t]);
        qf[kf][1] = f2tf32(Ps[(r0 + 8) * 68 + kk + t]);
        qf[kf][2] = f2tf32(Ps[r0 * 68 + kk + t + 4]);
        qf[kf][3] = f2tf32(Ps[(r0 + 8) * 68 + kk + t + 4]);
    }

    float m_r[2] = {-INFINITY, -INFINITY};
    float l_r[2] = {0.f, 0.f};
    float accO[8][4];
#pragma unroll
    for (int na = 0; na < 8; na++)
#pragma unroll
        for (int c = 0; c < 4; c++) accO[na][c] = 0.f;

    const int NT = S_ / 64;
    for (int kt = 0; kt < NT; kt++) {
        __syncthreads();   // prev iter's Ps & stage reads complete

        if (kt + 1 < NT) {
            const int k1 = (kt + 1) << 6;
            float* dK = KsB + ((kt + 1) & 1) * FT;
            float* dV = VsB + ((kt + 1) & 1) * FT;
#pragma unroll
            for (int l = 0; l < 8; l++) {
                const int f = tid + (l << 7);
                const int row = f >> 4, c4 = (f & 15) << 2;
                const size_t src = (size_t)(b * S_ + k1 + row) * D_ + h * DK_ + c4;
                unsigned dk = (unsigned)__cvta_generic_to_shared(&dK[row * 68 + c4]);
                unsigned dv = (unsigned)__cvta_generic_to_shared(&dV[row * 68 + c4]);
                asm volatile("cp.async.cg.shared.global [%0], [%1], 16;" :: "r"(dk), "l"(Kp + src));
                asm volatile("cp.async.cg.shared.global [%0], [%1], 16;" :: "r"(dv), "l"(V + src));
            }
            asm volatile("cp.async.commit_group;");
            asm volatile("cp.async.wait_group 1;");
        } else {
            asm volatile("cp.async.wait_group 0;");
        }
        __syncthreads();   // current stage visible to all warps

        const float* Ks = KsB + (kt & 1) * FT;
        const float* Vs = VsB + (kt & 1) * FT;
        const int k0 = kt << 6;

        // ---- S = Q K^T ----
        float sa[8][4];
#pragma unroll
        for (int na = 0; na < 8; na++)
#pragma unroll
            for (int c = 0; c < 4; c++) sa[na][c] = 0.f;

#pragma unroll
        for (int kf = 0; kf < 8; kf++) {
            const int kk = kf << 3;
            unsigned bk[8][2];
#pragma unroll
            for (int na = 0; na < 8; na++) {
                bk[na][0] = f2tf32(Ks[(8 * na + g) * 68 + kk + t]);
                bk[na][1] = f2tf32(Ks[(8 * na + g) * 68 + kk + t + 4]);
            }
#pragma unroll
            for (int na = 0; na < 8; na++) {
                asm volatile(
                    "mma.sync.aligned.m16n8k8.row.col.f32.tf32.tf32.f32 "
                    "{%0,%1,%2,%3}, {%4,%5,%6,%7}, {%8,%9}, {%0,%1,%2,%3};"
                    : "+f"(sa[na][0]), "+f"(sa[na][1]), "+f"(sa[na][2]), "+f"(sa[na][3])
                    : "r"(qf[kf][0]), "r"(qf[kf][1]), "r"(qf[kf][2]), "r"(qf[kf][3]),
                      "r"(bk[na][0]), "r"(bk[na][1]));
            }
        }

        // ---- masked online softmax (log2 domain, FFMA exp) ----
#pragma unroll
        for (int rh = 0; rh < 2; rh++) {
            const int ci = rh << 1;
            const size_t mrow = (size_t)(b * S_ + q0 + w * 16 + g + 8 * rh) * S_ + k0;
            int2 mk[8];
            float y[8][2];
            float mt = -INFINITY;
#pragma unroll
            for (int na = 0; na < 8; na++) {
                mk[na] = *(const int2*)(mask + mrow + 8 * na + 2 * t);
                y[na][0] = mk[na].x ? sa[na][ci]     * SCL : -INFINITY;
                y[na][1] = mk[na].y ? sa[na][ci + 1] * SCL : -INFINITY;
                mt = fmaxf(mt, fmaxf(y[na][0], y[na][1]));
            }
            mt = fmaxf(mt, __shfl_xor_sync(0xffffffffu, mt, 1));
            mt = fmaxf(mt, __shfl_xor_sync(0xffffffffu, mt, 2));
            const float mn = fmaxf(m_r[rh], mt);

            const float alpha = exp2c(m_r[rh] - mn);  // NaN-safe -> ~0; l=0 masks it
            float rs = 0.f;
            float pr[8][2];
#pragma unroll
            for (int na = 0; na < 8; na++) {
                const float p0 = mk[na].x ? exp2c(y[na][0] - mn) : 0.f;
                const float p1 = mk[na].y ? exp2c(y[na][1] - mn) : 0.f;
                pr[na][0] = p0; pr[na][1] = p1;
                rs += p0 + p1;
            }
            rs += __shfl_xor_sync(0xffffffffu, rs, 1);
            rs += __shfl_xor_sync(0xffffffffu, rs, 2);

            l_r[rh] = alpha * l_r[rh] + rs;
            m_r[rh] = mn;
#pragma unroll
            for (int na = 0; na < 8; na++) {
                accO[na][ci]     *= alpha;
                accO[na][ci + 1] *= alpha;
            }
            // store P as tf32 bit patterns
            float* prow = Ps + (w * 16 + g + 8 * rh) * 68 + 2 * t;
#pragma unroll
            for (int na = 0; na < 8; na++) {
                float2 st;
                st.x = __uint_as_float(f2tf32(pr[na][0]));
                st.y = __uint_as_float(f2tf32(pr[na][1]));
                *(float2*)(prow + 8 * na) = st;
            }
        }
        __syncthreads();   // Ps visible

        // ---- O += P V ----
#pragma unroll
        for (int kf = 0; kf < 8; kf++) {
            const int kk = kf << 3;
            unsigned pa[4];
            pa[0] = __float_as_uint(Ps[r0 * 68 + kk + t]);
            pa[1] = __float_as_uint(Ps[(r0 + 8) * 68 + kk + t]);
            pa[2] = __float_as_uint(Ps[r0 * 68 + kk + t + 4]);
            pa[3] = __float_as_uint(Ps[(r0 + 8) * 68 + kk + t + 4]);
            unsigned bv[8][2];
#pragma unroll
            for (int na = 0; na < 8; na++) {
                bv[na][0] = f2tf32(Vs[(kk + t) * 68 + 8 * na + g]);
                bv[na][1] = f2tf32(Vs[(kk + t + 4) * 68 + 8 * na + g]);
            }
#pragma unroll
            for (int na = 0; na < 8; na++) {
                asm volatile(
                    "mma.sync.aligned.m16n8k8.row.col.f32.tf32.tf32.f32 "
                    "{%0,%1,%2,%3}, {%4,%5,%6,%7}, {%8,%9}, {%0,%1,%2,%3};"
                    : "+f"(accO[na][0]), "+f"(accO[na][1]), "+f"(accO[na][2]), "+f"(accO[na][3])
                    : "r"(pa[0]), "r"(pa[1]), "r"(pa[2]), "r"(pa[3]),
                      "r"(bv[na][0]), "r"(bv[na][1]));
            }
        }
    }

    // ---- normalize + write ----
#pragma unroll
    for (int rh = 0; rh < 2; rh++) {
        const int ci = rh << 1;
        const float inv = (l_r[rh] > 0.f) ? __frcp_rn(l_r[rh]) : 0.f;
        const size_t orow = (size_t)(b * S_ + q0 + w * 16 + g + 8 * rh) * D_ + h * DK_;
#pragma unroll
        for (int na = 0; na < 8; na++) {
            float2 r;
            r.x = accO[na][ci]     * inv;
            r.y = accO[na][ci + 1] * inv;
            *(float2*)(O + orow + 8 * na + 2 * t) = r;
        }
    }
}

// ---------------------------------------------------------------------------
extern "C" void kernel_launch(void* const* d_in, const int* in_sizes, int n_in,
                              void* d_out, int out_size) {
    (void)in_sizes; (void)n_in; (void)out_size;
    const float* query = (const float*)d_in[0];
    const float* key   = (const float*)d_in[1];
    const float* value = (const float*)d_in[2];
    const int*   msk   = (const int*)  d_in[3];
    const float* wq = (const float*)d_in[4];  const float* bq = (const float*)d_in[5];
    const float* wk = (const float*)d_in[6];  const float* bk = (const float*)d_in[7];
    const float* wv = (const float*)d_in[8];  const float* bv = (const float*)d_in[9];
    const float* wo = (const float*)d_in[10]; const float* bo = (const float*)d_in[11];
    float* out = (float*)d_out;

    float *gq, *gk, *gv, *ga;
    cudaGetSymbolAddress((void**)&gq, g_q);
    cudaGetSymbolAddress((void**)&gk, g_k);
    cudaGetSymbolAddress((void**)&gv, g_v);
    cudaGetSymbolAddress((void**)&ga, g_att);

    const int M = B_ * S_;
    const dim3 gGrid(D_ / 128, M / 128);
    const int gemm_smem  = 4 * TILE_F * sizeof(float);  // 73728 B
    const int flash_smem = 5 * FT * sizeof(float);      // 87040 B

    static bool attr_set = false;
    if (!attr_set) {
        cudaFuncSetAttribute(gemm_tf32, cudaFuncAttributeMaxDynamicSharedMemorySize, gemm_smem);
        cudaFuncSetAttribute(flash_tc, cudaFuncAttributeMaxDynamicSharedMemorySize, flash_smem);
        attr_set = true;
    }

    gemm_tf32<<<gGrid, 256, gemm_smem>>>(query, wq, bq, gq, M, D_, D_);
    gemm_tf32<<<gGrid, 256, gemm_smem>>>(key,   wk, bk, gk, M, D_, D_);
    gemm_tf32<<<gGrid, 256, gemm_smem>>>(value, wv, bv, gv, M, D_, D_);

    flash_tc<<<dim3(S_ / 64, B_ * H_), 128, flash_smem>>>(gq, gk, gv, msk, ga);

    gemm_tf32<<<gGrid, 256, gemm_smem>>>(ga, wo, bo, out, M, D_, D_);
}

// round 5
// speedup vs baseline: 1.6111x; 1.6111x over previous
#include <cuda_runtime.h>
#include <math.h>

#define B_  8
#define S_  1024
#define D_  1024
#define H_  16
#define DK_ 64

// Scratch (device globals: no allocation allowed in kernel_launch)
__device__ float g_q[B_*S_*D_];
__device__ float g_k[B_*S_*D_];
__device__ float g_v[B_*S_*D_];
__device__ float g_att[B_*S_*D_];

__device__ __forceinline__ unsigned f2tf32(float x) {
    unsigned u;
    asm("cvt.rna.tf32.f32 %0, %1;" : "=r"(u) : "f"(x));
    return u;
}

// Branchless exp2 for z <= 0, FFMA/ALU only (no MUFU).
__device__ __forceinline__ float exp2c(float z) {
    z = fmaxf(z, -126.0f);
    const float magic = 12582912.0f;           // 1.5*2^23
    float r = z + magic;
    int   n = __float_as_int(r) - __float_as_int(magic);
    float f = z - (r - magic);                 // f in [-0.5, 0.5]
    float c = 0.0013333558f;
    c = fmaf(c, f, 0.0096181291f);
    c = fmaf(c, f, 0.0555041087f);
    c = fmaf(c, f, 0.2402265069f);
    c = fmaf(c, f, 0.6931471806f);
    c = fmaf(c, f, 1.0f);
    return c * __int_as_float((n + 127) << 23);
}

// ---------------------------------------------------------------------------
// tf32 tensor-core GEMM: C[M,N] = A[M,K] @ W[N,K]^T + bias[N]
// out_tf32 != 0: store tf32-rounded bit patterns (for Q/K/V feeding flash).
// ---------------------------------------------------------------------------
#define TILE_F 4608   // 128*36 floats per smem tile

__global__ void __launch_bounds__(256) gemm_tf32(
    const float* __restrict__ A, const float* __restrict__ W,
    const float* __restrict__ bias, float* __restrict__ C,
    int M, int N, int K, int out_tf32)
{
    extern __shared__ float sm[];
    const int tid  = threadIdx.x;
    const int warp = tid >> 5, lane = tid & 31;
    const int wm = warp & 1, wn = warp >> 1;
    const int g = lane >> 2, t = lane & 3;
    const int m0 = blockIdx.y << 7, n0 = blockIdx.x << 7;

    const int lrow = tid >> 3;
    const int lcol = (tid & 7) << 2;

    float acc[4][4][4];
#pragma unroll
    for (int i = 0; i < 4; i++)
#pragma unroll
        for (int j = 0; j < 4; j++)
#pragma unroll
            for (int c = 0; c < 4; c++) acc[i][j][c] = 0.f;

    const int NCHUNK = K >> 5;

    {
        float* sA = sm;
        float* sW = sm + TILE_F;
#pragma unroll
        for (int l = 0; l < 4; l++) {
            const int row = lrow + (l << 5);
            unsigned da = (unsigned)__cvta_generic_to_shared(&sA[row * 36 + lcol]);
            unsigned dw = (unsigned)__cvta_generic_to_shared(&sW[row * 36 + lcol]);
            const float* ga = A + (size_t)(m0 + row) * K + lcol;
            const float* gw = W + (size_t)(n0 + row) * K + lcol;
            asm volatile("cp.async.cg.shared.global [%0], [%1], 16;" :: "r"(da), "l"(ga));
            asm volatile("cp.async.cg.shared.global [%0], [%1], 16;" :: "r"(dw), "l"(gw));
        }
        asm volatile("cp.async.commit_group;");
    }

    for (int kc = 0; kc < NCHUNK; kc++) {
        if (kc + 1 < NCHUNK) {
            const int k0 = (kc + 1) << 5;
            float* sA = sm + ((kc + 1) & 1) * (2 * TILE_F);
            float* sW = sA + TILE_F;
#pragma unroll
            for (int l = 0; l < 4; l++) {
                const int row = lrow + (l << 5);
                unsigned da = (unsigned)__cvta_generic_to_shared(&sA[row * 36 + lcol]);
                unsigned dw = (unsigned)__cvta_generic_to_shared(&sW[row * 36 + lcol]);
                const float* ga = A + (size_t)(m0 + row) * K + k0 + lcol;
                const float* gw = W + (size_t)(n0 + row) * K + k0 + lcol;
                asm volatile("cp.async.cg.shared.global [%0], [%1], 16;" :: "r"(da), "l"(ga));
                asm volatile("cp.async.cg.shared.global [%0], [%1], 16;" :: "r"(dw), "l"(gw));
            }
            asm volatile("cp.async.commit_group;");
            asm volatile("cp.async.wait_group 1;");
        } else {
            asm volatile("cp.async.wait_group 0;");
        }
        __syncthreads();

        const float* sA = sm + (kc & 1) * (2 * TILE_F);
        const float* sW = sA + TILE_F;

#pragma unroll
        for (int ks = 0; ks < 4; ks++) {
            const int kk = ks << 3;
            unsigned af[4][4], bf[4][2];
#pragma unroll
            for (int ma = 0; ma < 4; ma++) {
                const int r0 = wm * 64 + ma * 16 + g;
                af[ma][0] = f2tf32(sA[r0 * 36 + kk + t]);
                af[ma][1] = f2tf32(sA[(r0 + 8) * 36 + kk + t]);
                af[ma][2] = f2tf32(sA[r0 * 36 + kk + t + 4]);
                af[ma][3] = f2tf32(sA[(r0 + 8) * 36 + kk + t + 4]);
            }
#pragma unroll
            for (int na = 0; na < 4; na++) {
                const int rn = wn * 32 + na * 8 + g;
                bf[na][0] = f2tf32(sW[rn * 36 + kk + t]);
                bf[na][1] = f2tf32(sW[rn * 36 + kk + t + 4]);
            }
#pragma unroll
            for (int ma = 0; ma < 4; ma++)
#pragma unroll
                for (int na = 0; na < 4; na++) {
                    asm volatile(
                        "mma.sync.aligned.m16n8k8.row.col.f32.tf32.tf32.f32 "
                        "{%0,%1,%2,%3}, {%4,%5,%6,%7}, {%8,%9}, {%0,%1,%2,%3};"
                        : "+f"(acc[ma][na][0]), "+f"(acc[ma][na][1]),
                          "+f"(acc[ma][na][2]), "+f"(acc[ma][na][3])
                        : "r"(af[ma][0]), "r"(af[ma][1]), "r"(af[ma][2]), "r"(af[ma][3]),
                          "r"(bf[na][0]), "r"(bf[na][1]));
                }
        }
        __syncthreads();
    }

#pragma unroll
    for (int na = 0; na < 4; na++) {
        const int col = n0 + wn * 32 + na * 8 + 2 * t;
        const float bx = bias[col], by = bias[col + 1];
#pragma unroll
        for (int ma = 0; ma < 4; ma++) {
            const int row0 = m0 + wm * 64 + ma * 16 + g;
            float2 r;
            r.x = acc[ma][na][0] + bx; r.y = acc[ma][na][1] + by;
            if (out_tf32) {
                r.x = __uint_as_float(f2tf32(r.x));
                r.y = __uint_as_float(f2tf32(r.y));
            }
            *(float2*)(C + (size_t)row0 * N + col) = r;
            r.x = acc[ma][na][2] + bx; r.y = acc[ma][na][3] + by;
            if (out_tf32) {
                r.x = __uint_as_float(f2tf32(r.x));
                r.y = __uint_as_float(f2tf32(r.y));
            }
            *(float2*)(C + (size_t)(row0 + 8) * N + col) = r;
        }
    }
}

// ---------------------------------------------------------------------------
// Tensor-core flash attention. Q/K/V arrive as tf32 bit patterns (from the
// projection GEMM epilogues) -> zero conversions in the mainloop.
// CTA = 256 threads = 8 warps, 128 q-rows (16 per warp), k-tile 64.
// K/P stride 68 (row-frag conflict-free); V stride 72 (col-frag conflict-free).
// ---------------------------------------------------------------------------
#define KSTR 68
#define VSTR 72
#define KT (64 * KSTR)   // 4352 floats
#define VT (64 * VSTR)   // 4608 floats
#define PSOFF (2 * KT + 2 * VT)
#define FLASH_SMEM ((PSOFF + 128 * 68) * 4)   // 106496 bytes

__global__ void __launch_bounds__(256) flash_tc(
    const float* __restrict__ Q, const float* __restrict__ Kp,
    const float* __restrict__ V, const int* __restrict__ mask,
    float* __restrict__ O)
{
    extern __shared__ float smf[];
    float* KsB = smf;                 // [2][64][68]
    float* VsB = smf + 2 * KT;        // [2][64][72]
    float* Ps  = smf + PSOFF;         // [128][68] (P tile / Q & O staging)

    const int tid  = threadIdx.x;
    const int w    = tid >> 5, lane = tid & 31;
    const int g    = lane >> 2, t = lane & 3;
    const int q0   = (int)blockIdx.x << 7;
    const int bh   = blockIdx.y;
    const int b    = bh >> 4, h = bh & 15;
    const float SCL = 0.125f * 1.4426950408889634f;  // scale * log2(e)

    // prefetch K/V tile 0
    {
#pragma unroll
        for (int l = 0; l < 4; l++) {
            const int f = tid + (l << 8);
            const int row = f >> 4, c4 = (f & 15) << 2;
            const size_t src = (size_t)(b * S_ + row) * D_ + h * DK_ + c4;
            unsigned dk = (unsigned)__cvta_generic_to_shared(&KsB[row * KSTR + c4]);
            unsigned dv = (unsigned)__cvta_generic_to_shared(&VsB[row * VSTR + c4]);
            asm volatile("cp.async.cg.shared.global [%0], [%1], 16;" :: "r"(dk), "l"(Kp + src));
            asm volatile("cp.async.cg.shared.global [%0], [%1], 16;" :: "r"(dv), "l"(V + src));
        }
        asm volatile("cp.async.commit_group;");
    }

    // stage Q (128 rows x 64) into Ps, then load fragments (already tf32 bits)
#pragma unroll
    for (int l = 0; l < 8; l++) {
        const int f = tid + (l << 8);
        const int row = f >> 4, c4 = (f & 15) << 2;
        *(float4*)&Ps[row * 68 + c4] =
            *(const float4*)(Q + (size_t)(b * S_ + q0 + row) * D_ + h * DK_ + c4);
    }
    __syncthreads();

    const int r0 = w * 16 + g;
    unsigned qf[8][4];
#pragma unroll
    for (int kf = 0; kf < 8; kf++) {
        const int kk = kf << 3;
        qf[kf][0] = __float_as_uint(Ps[r0 * 68 + kk + t]);
        qf[kf][1] = __float_as_uint(Ps[(r0 + 8) * 68 + kk + t]);
        qf[kf][2] = __float_as_uint(Ps[r0 * 68 + kk + t + 4]);
        qf[kf][3] = __float_as_uint(Ps[(r0 + 8) * 68 + kk + t + 4]);
    }

    float m_r[2] = {-INFINITY, -INFINITY};
    float l_r[2] = {0.f, 0.f};
    float accO[8][4];
#pragma unroll
    for (int na = 0; na < 8; na++)
#pragma unroll
        for (int c = 0; c < 4; c++) accO[na][c] = 0.f;

    const int NT = S_ / 64;
    for (int kt = 0; kt < NT; kt++) {
        __syncthreads();   // prev iter's Ps/Vs reads (and Q-frag reads) done

        if (kt + 1 < NT) {
            const int k1 = (kt + 1) << 6;
            float* dK = KsB + ((kt + 1) & 1) * KT;
            float* dV = VsB + ((kt + 1) & 1) * VT;
#pragma unroll
            for (int l = 0; l < 4; l++) {
                const int f = tid + (l << 8);
                const int row = f >> 4, c4 = (f & 15) << 2;
                const size_t src = (size_t)(b * S_ + k1 + row) * D_ + h * DK_ + c4;
                unsigned dk = (unsigned)__cvta_generic_to_shared(&dK[row * KSTR + c4]);
                unsigned dv = (unsigned)__cvta_generic_to_shared(&dV[row * VSTR + c4]);
                asm volatile("cp.async.cg.shared.global [%0], [%1], 16;" :: "r"(dk), "l"(Kp + src));
                asm volatile("cp.async.cg.shared.global [%0], [%1], 16;" :: "r"(dv), "l"(V + src));
            }
            asm volatile("cp.async.commit_group;");
            asm volatile("cp.async.wait_group 1;");
        } else {
            asm volatile("cp.async.wait_group 0;");
        }
        __syncthreads();   // current stage visible

        const float* Ks = KsB + (kt & 1) * KT;
        const float* Vs = VsB + (kt & 1) * VT;
        const int k0 = kt << 6;

        // ---- S = Q K^T ----
        float sa[8][4];
#pragma unroll
        for (int na = 0; na < 8; na++)
#pragma unroll
            for (int c = 0; c < 4; c++) sa[na][c] = 0.f;

#pragma unroll
        for (int kf = 0; kf < 8; kf++) {
            const int kk = kf << 3;
            unsigned bk[8][2];
#pragma unroll
            for (int na = 0; na < 8; na++) {
                bk[na][0] = __float_as_uint(Ks[(8 * na + g) * KSTR + kk + t]);
                bk[na][1] = __float_as_uint(Ks[(8 * na + g) * KSTR + kk + t + 4]);
            }
#pragma unroll
            for (int na = 0; na < 8; na++) {
                asm volatile(
                    "mma.sync.aligned.m16n8k8.row.col.f32.tf32.tf32.f32 "
                    "{%0,%1,%2,%3}, {%4,%5,%6,%7}, {%8,%9}, {%0,%1,%2,%3};"
                    : "+f"(sa[na][0]), "+f"(sa[na][1]), "+f"(sa[na][2]), "+f"(sa[na][3])
                    : "r"(qf[kf][0]), "r"(qf[kf][1]), "r"(qf[kf][2]), "r"(qf[kf][3]),
                      "r"(bk[na][0]), "r"(bk[na][1]));
            }
        }

        // ---- masked online softmax (log2 domain, FFMA exp) ----
#pragma unroll
        for (int rh = 0; rh < 2; rh++) {
            const int ci = rh << 1;
            const size_t mrow = (size_t)(b * S_ + q0 + w * 16 + g + 8 * rh) * S_ + k0;
            int2 mk[8];
            float y[8][2];
            float mt = -INFINITY;
#pragma unroll
            for (int na = 0; na < 8; na++) {
                mk[na] = *(const int2*)(mask + mrow + 8 * na + 2 * t);
                y[na][0] = mk[na].x ? sa[na][ci]     * SCL : -INFINITY;
                y[na][1] = mk[na].y ? sa[na][ci + 1] * SCL : -INFINITY;
                mt = fmaxf(mt, fmaxf(y[na][0], y[na][1]));
            }
            mt = fmaxf(mt, __shfl_xor_sync(0xffffffffu, mt, 1));
            mt = fmaxf(mt, __shfl_xor_sync(0xffffffffu, mt, 2));
            const float mn = fmaxf(m_r[rh], mt);

            const float alpha = exp2c(m_r[rh] - mn);
            float rs = 0.f;
            float pr[8][2];
#pragma unroll
            for (int na = 0; na < 8; na++) {
                const float p0 = mk[na].x ? exp2c(y[na][0] - mn) : 0.f;
                const float p1 = mk[na].y ? exp2c(y[na][1] - mn) : 0.f;
                pr[na][0] = p0; pr[na][1] = p1;
                rs += p0 + p1;
            }
            rs += __shfl_xor_sync(0xffffffffu, rs, 1);
            rs += __shfl_xor_sync(0xffffffffu, rs, 2);

            l_r[rh] = alpha * l_r[rh] + rs;
            m_r[rh] = mn;
#pragma unroll
            for (int na = 0; na < 8; na++) {
                accO[na][ci]     *= alpha;
                accO[na][ci + 1] *= alpha;
            }
            float* prow = Ps + (w * 16 + g + 8 * rh) * 68 + 2 * t;
#pragma unroll
            for (int na = 0; na < 8; na++) {
                float2 st;
                st.x = __uint_as_float(f2tf32(pr[na][0]));
                st.y = __uint_as_float(f2tf32(pr[na][1]));
                *(float2*)(prow + 8 * na) = st;
            }
        }
        __syncthreads();   // Ps visible

        // ---- O += P V ----
#pragma unroll
        for (int kf = 0; kf < 8; kf++) {
            const int kk = kf << 3;
            unsigned pa[4];
            pa[0] = __float_as_uint(Ps[r0 * 68 + kk + t]);
            pa[1] = __float_as_uint(Ps[(r0 + 8) * 68 + kk + t]);
            pa[2] = __float_as_uint(Ps[r0 * 68 + kk + t + 4]);
            pa[3] = __float_as_uint(Ps[(r0 + 8) * 68 + kk + t + 4]);
            unsigned bv[8][2];
#pragma unroll
            for (int na = 0; na < 8; na++) {
                bv[na][0] = __float_as_uint(Vs[(kk + t) * VSTR + 8 * na + g]);
                bv[na][1] = __float_as_uint(Vs[(kk + t + 4) * VSTR + 8 * na + g]);
            }
#pragma unroll
            for (int na = 0; na < 8; na++) {
                asm volatile(
                    "mma.sync.aligned.m16n8k8.row.col.f32.tf32.tf32.f32 "
                    "{%0,%1,%2,%3}, {%4,%5,%6,%7}, {%8,%9}, {%0,%1,%2,%3};"
                    : "+f"(accO[na][0]), "+f"(accO[na][1]), "+f"(accO[na][2]), "+f"(accO[na][3])
                    : "r"(pa[0]), "r"(pa[1]), "r"(pa[2]), "r"(pa[3]),
                      "r"(bv[na][0]), "r"(bv[na][1]));
            }
        }
    }

    // ---- normalize, stage in smem, coalesced write ----
    __syncthreads();  // last tile's Ps reads done before O staging overwrites
#pragma unroll
    for (int rh = 0; rh < 2; rh++) {
        const int ci = rh << 1;
        const float inv = (l_r[rh] > 0.f) ? __frcp_rn(l_r[rh]) : 0.f;
        float* prow = Ps + (w * 16 + g + 8 * rh) * 68 + 2 * t;
#pragma unroll
        for (int na = 0; na < 8; na++) {
            float2 r;
            r.x = accO[na][ci]     * inv;
            r.y = accO[na][ci + 1] * inv;
            *(float2*)(prow + 8 * na) = r;
        }
    }
    __syncthreads();
#pragma unroll
    for (int l = 0; l < 8; l++) {
        const int f = tid + (l << 8);
        const int row = f >> 4, c4 = (f & 15) << 2;
        *(float4*)(O + (size_t)(b * S_ + q0 + row) * D_ + h * DK_ + c4) =
            *(float4*)&Ps[row * 68 + c4];
    }
}

// ---------------------------------------------------------------------------
extern "C" void kernel_launch(void* const* d_in, const int* in_sizes, int n_in,
                              void* d_out, int out_size) {
    (void)in_sizes; (void)n_in; (void)out_size;
    const float* query = (const float*)d_in[0];
    const float* key   = (const float*)d_in[1];
    const float* value = (const float*)d_in[2];
    const int*   msk   = (const int*)  d_in[3];
    const float* wq = (const float*)d_in[4];  const float* bq = (const float*)d_in[5];
    const float* wk = (const float*)d_in[6];  const float* bk = (const float*)d_in[7];
    const float* wv = (const float*)d_in[8];  const float* bv = (const float*)d_in[9];
    const float* wo = (const float*)d_in[10]; const float* bo = (const float*)d_in[11];
    float* out = (float*)d_out;

    float *gq, *gk, *gv, *ga;
    cudaGetSymbolAddress((void**)&gq, g_q);
    cudaGetSymbolAddress((void**)&gk, g_k);
    cudaGetSymbolAddress((void**)&gv, g_v);
    cudaGetSymbolAddress((void**)&ga, g_att);

    const int M = B_ * S_;
    const dim3 gGrid(D_ / 128, M / 128);
    const int gemm_smem = 4 * TILE_F * sizeof(float);  // 73728 B

    static bool attr_set = false;
    if (!attr_set) {
        cudaFuncSetAttribute(gemm_tf32, cudaFuncAttributeMaxDynamicSharedMemorySize, gemm_smem);
        cudaFuncSetAttribute(flash_tc, cudaFuncAttributeMaxDynamicSharedMemorySize, FLASH_SMEM);
        attr_set = true;
    }

    gemm_tf32<<<gGrid, 256, gemm_smem>>>(query, wq, bq, gq, M, D_, D_, 1);
    gemm_tf32<<<gGrid, 256, gemm_smem>>>(key,   wk, bk, gk, M, D_, D_, 1);
    gemm_tf32<<<gGrid, 256, gemm_smem>>>(value, wv, bv, gv, M, D_, D_, 1);

    flash_tc<<<dim3(S_ / 128, B_ * H_), 256, FLASH_SMEM>>>(gq, gk, gv, msk, ga);

    gemm_tf32<<<gGrid, 256, gemm_smem>>>(ga, wo, bo, out, M, D_, D_, 0);
}